// round 13
// baseline (speedup 1.0000x reference)
#include <cuda_runtime.h>
#include <cuda_bf16.h>
#include <cstdint>
#include <math.h>

#define BB   16
#define CC   256
#define NN   16384
#define KK   64
#define TEMPF 20.0f
#define EPSF  1e-6f
#define EM_STEPS 3
#define NSPLIT 32
#define NBLK1 (NN/128)      // 128 GEMM1 n-blocks

// -------- scratch (no allocations allowed -> device globals) --------
__device__ __align__(16) __nv_bfloat16 g_xthi[(size_t)BB*NN*CC];  // x^T hi [b][n][c]
__device__ __align__(16) __nv_bfloat16 g_xtlo[(size_t)BB*NN*CC];
__device__ __align__(16) __nv_bfloat16 g_xchi[(size_t)BB*CC*NN];  // x hi   [b][c][n]
__device__ __align__(16) __nv_bfloat16 g_xclo[(size_t)BB*CC*NN];
__device__ __align__(16) __nv_bfloat16 g_zthi[(size_t)BB*KK*NN];  // z^T hi [b][k][n]
__device__ __align__(16) __nv_bfloat16 g_ztlo[(size_t)BB*KK*NN];
__device__ __align__(16) __nv_bfloat16 g_mthi[BB*KK*CC];          // m^T hi [b][k][c]
__device__ __align__(16) __nv_bfloat16 g_mtlo[BB*KK*CC];
__device__ float g_mtmp [BB*CC*KK];
__device__ float g_S    [BB*KK];
__device__ float g_Spart[NBLK1*BB*KK];
__device__ float g_part [(size_t)BB*NSPLIT*CC*KK];

// -------- helpers --------
__device__ __forceinline__ uint32_t smem_u32(const void* p) {
    uint32_t a;
    asm("{ .reg .u64 t; cvta.to.shared.u64 t, %1; cvt.u32.u64 %0, t; }" : "=r"(a) : "l"(p));
    return a;
}
__device__ __forceinline__ void ldm_x4(uint32_t r[4], uint32_t addr) {
    asm volatile("ldmatrix.sync.aligned.m8n8.x4.shared.b16 {%0,%1,%2,%3}, [%4];"
        : "=r"(r[0]), "=r"(r[1]), "=r"(r[2]), "=r"(r[3]) : "r"(addr));
}
__device__ __forceinline__ void mma16816(float c[4], const uint32_t a[4], uint32_t b0, uint32_t b1) {
    asm volatile("mma.sync.aligned.m16n8k16.row.col.f32.bf16.bf16.f32 "
        "{%0,%1,%2,%3}, {%4,%5,%6,%7}, {%8,%9}, {%0,%1,%2,%3};"
        : "+f"(c[0]), "+f"(c[1]), "+f"(c[2]), "+f"(c[3])
        : "r"(a[0]), "r"(a[1]), "r"(a[2]), "r"(a[3]), "r"(b0), "r"(b1));
}
__device__ __forceinline__ void split_bf16(float v, __nv_bfloat16& hi, __nv_bfloat16& lo) {
    hi = __float2bfloat16_rn(v);
    lo = __float2bfloat16_rn(v - __bfloat162float(hi));
}
#define CP16(d, s)  asm volatile("cp.async.cg.shared.global [%0], [%1], 16;" :: "r"(d), "l"(s))
#define CP_COMMIT() asm volatile("cp.async.commit_group;" ::: "memory")
#define CP_WAIT1()  asm volatile("cp.async.wait_group 1;" ::: "memory")
#define CP_WAIT0()  asm volatile("cp.async.wait_group 0;" ::: "memory")

// smem layouts over one dynamic buffer (2-stage pipeline)
struct Tiles {                                   // one pipeline stage: 30720 B
    __nv_bfloat16 ah[128][40], al[128][40];      // A rows x 32ctr (+8 pad)
    __nv_bfloat16 bh[64][40],  bl[64][40];       // B^T: 64 k-rows x 32ctr (+8 pad)
};
struct E0 { __nv_bfloat16 zh[64][144], zl[64][144]; };  // 36864 B
struct E1 { float zs[128][72]; };                        // 36864 B
#define SMEM_MAIN 61440                           // 2 * sizeof(Tiles)

// -------- prepass: x [b][c][n] fp32 -> split bf16 in both orientations --------
__global__ void k_prep(const float* __restrict__ x) {
    __shared__ float tbuf[32][33];
    const int b = blockIdx.z, n0 = blockIdx.x * 32, c0 = blockIdx.y * 32;
    const int tx = threadIdx.x, ty = threadIdx.y;
#pragma unroll
    for (int j = 0; j < 4; j++) {
        int c = c0 + ty + 8 * j;
        size_t o = ((size_t)b * CC + c) * NN + n0 + tx;
        float v = x[o];
        tbuf[ty + 8 * j][tx] = v;
        __nv_bfloat16 hi, lo; split_bf16(v, hi, lo);
        g_xchi[o] = hi; g_xclo[o] = lo;
    }
    __syncthreads();
#pragma unroll
    for (int j = 0; j < 4; j++) {
        float v = tbuf[tx][ty + 8 * j];
        __nv_bfloat16 hi, lo; split_bf16(v, hi, lo);
        size_t o = ((size_t)b * NN + n0 + ty + 8 * j) * CC + c0 + tx;
        g_xthi[o] = hi; g_xtlo[o] = lo;
    }
}

// -------- init m^T from mu (broadcast over batches) --------
__global__ void k_initm(const float* __restrict__ mu) {
    int idx = blockIdx.x * 256 + threadIdx.x;       // over B*K*C, c fastest
    int c = idx & (CC - 1);
    int k = (idx >> 8) & (KK - 1);
    __nv_bfloat16 hi, lo; split_bf16(mu[c * KK + k], hi, lo);
    g_mthi[idx] = hi; g_mtlo[idx] = lo;
}

// ---- unified MMA kernel (2-stage cp.async pipeline, ldmatrix A+B) ----
// __launch_bounds__(256, 3): cap regs at 84 to fit 3 CTAs/SM (occupancy was the
// binding constraint at 128 regs / 2 CTAs). Spills should land on cold epilogue values.
// EPI 0: GEMM1 EM step  : softmax(TEMP*logits) -> z^T split bf16 + column-sum partials
// EPI 1: GEMM1 final    : softmax(logits) -> fp32 z to d_out
// EPI 2: GEMM2 partials : raw fp32 partial sums to g_part
template<int EPI>
__global__ void __launch_bounds__(256, 3)
k_mma(float* __restrict__ zout) {
    extern __shared__ __align__(16) char dynsmem[];
    Tiles* tiles = (Tiles*)dynsmem;
    E0* e0 = (E0*)dynsmem;
    E1* e1 = (E1*)dynsmem;

    const int tid  = threadIdx.x;
    const int lane = tid & 31, warp = tid >> 5;
    const int g = lane >> 2, t = lane & 3;
    const int warp_row = warp * 16;

    const __nv_bfloat16 *Ah, *Al, *Bh, *Bl;
    size_t sA, sB; int ctr0, iters, b, rowbase;
    if (EPI < 2) {
        b = blockIdx.y; rowbase = blockIdx.x * 128;
        Ah = g_xthi + ((size_t)b * NN + rowbase) * CC;
        Al = g_xtlo + ((size_t)b * NN + rowbase) * CC;
        Bh = g_mthi + (size_t)b * KK * CC;
        Bl = g_mtlo + (size_t)b * KK * CC;
        sA = CC; sB = CC; ctr0 = 0; iters = CC / 32;
    } else {
        b = blockIdx.z; rowbase = blockIdx.x * 128;
        Ah = g_xchi + ((size_t)b * CC + rowbase) * NN;
        Al = g_xclo + ((size_t)b * CC + rowbase) * NN;
        Bh = g_zthi + (size_t)b * KK * NN;
        Bl = g_ztlo + (size_t)b * KK * NN;
        sA = NN; sB = NN;
        ctr0 = blockIdx.y * (NN / NSPLIT); iters = (NN / NSPLIT) / 32;
    }

    float acc[8][4];
#pragma unroll
    for (int j = 0; j < 8; j++)
#pragma unroll
        for (int r = 0; r < 4; r++) acc[j][r] = 0.0f;

    const int lrow = tid >> 1, lseg = tid & 1;     // A fill: 128 rows x 2 segs
    const int brow = tid >> 2, bseg = tid & 3;     // B fill: 64 rows x 4 segs

    // async fill of one stage (A: 2 CP16/array/thread, B: 1 CP16/array/thread)
    auto fill = [&](int it, int buf) {
        const int c0 = ctr0 + it * 32;
        Tiles& T = tiles[buf];
        {
            uint32_t d = smem_u32(&T.ah[lrow][lseg * 16]);
            const __nv_bfloat16* s = Ah + (size_t)lrow * sA + c0 + lseg * 16;
            CP16(d, s); CP16(d + 16, s + 8);
            d = smem_u32(&T.al[lrow][lseg * 16]);
            s = Al + (size_t)lrow * sA + c0 + lseg * 16;
            CP16(d, s); CP16(d + 16, s + 8);
        }
        {
            uint32_t d = smem_u32(&T.bh[brow][bseg * 8]);
            const __nv_bfloat16* s = Bh + (size_t)brow * sB + c0 + bseg * 8;
            CP16(d, s);
            d = smem_u32(&T.bl[brow][bseg * 8]);
            s = Bl + (size_t)brow * sB + c0 + bseg * 8;
            CP16(d, s);
        }
        CP_COMMIT();
    };

    fill(0, 0);
    for (int it = 0; it < iters; it++) {
        if (it + 1 < iters) { fill(it + 1, (it + 1) & 1); CP_WAIT1(); }
        else                { CP_WAIT0(); }
        __syncthreads();
        Tiles& T = tiles[it & 1];

#pragma unroll
        for (int ks = 0; ks < 2; ks++) {
            const int lr = lane & 7, lq = lane >> 3;
            uint32_t ah4[4], al4[4];
            ldm_x4(ah4, smem_u32(&T.ah[warp_row + lr + (lq & 1) * 8][ks * 16 + (lq >> 1) * 8]));
            ldm_x4(al4, smem_u32(&T.al[warp_row + lr + (lq & 1) * 8][ks * 16 + (lq >> 1) * 8]));
            // B fragments via ldmatrix.x4, consumed immediately (2 j-tiles per jp)
#pragma unroll
            for (int jp = 0; jp < 4; jp++) {
                uint32_t bh4[4], bl4[4];
                ldm_x4(bh4, smem_u32(&T.bh[jp * 16 + (lq >> 1) * 8 + lr][ks * 16 + (lq & 1) * 8]));
                ldm_x4(bl4, smem_u32(&T.bl[jp * 16 + (lq >> 1) * 8 + lr][ks * 16 + (lq & 1) * 8]));
                mma16816(acc[jp * 2    ], ah4, bh4[0], bh4[1]);   // hi*hi
                mma16816(acc[jp * 2    ], ah4, bl4[0], bl4[1]);   // hi*lo
                mma16816(acc[jp * 2    ], al4, bh4[0], bh4[1]);   // lo*hi
                mma16816(acc[jp * 2 + 1], ah4, bh4[2], bh4[3]);
                mma16816(acc[jp * 2 + 1], ah4, bl4[2], bl4[3]);
                mma16816(acc[jp * 2 + 1], al4, bh4[2], bh4[3]);
            }
        }
        __syncthreads();
    }

    if (EPI == 2) {
#pragma unroll
        for (int j = 0; j < 8; j++) {
            e1->zs[warp_row + g    ][8 * j + 2 * t    ] = acc[j][0];
            e1->zs[warp_row + g    ][8 * j + 2 * t + 1] = acc[j][1];
            e1->zs[warp_row + g + 8][8 * j + 2 * t    ] = acc[j][2];
            e1->zs[warp_row + g + 8][8 * j + 2 * t + 1] = acc[j][3];
        }
        __syncthreads();
        const int split = blockIdx.y;
        float* dst = g_part + (((size_t)(b * NSPLIT + split)) * CC + rowbase + lrow) * KK + lseg * 32;
        const float* src = &e1->zs[lrow][lseg * 32];
#pragma unroll
        for (int q = 0; q < 8; q++) ((float4*)dst)[q] = ((const float4*)src)[q];
        return;
    }

    // GEMM1 epilogues: softmax over k (rows warp_row+g and warp_row+g+8)
    const float sc = (EPI == 0) ? TEMPF : 1.0f;
    float mxA = -1e30f, mxB = -1e30f;
#pragma unroll
    for (int j = 0; j < 8; j++) {
        acc[j][0] *= sc; acc[j][1] *= sc; acc[j][2] *= sc; acc[j][3] *= sc;
        mxA = fmaxf(mxA, fmaxf(acc[j][0], acc[j][1]));
        mxB = fmaxf(mxB, fmaxf(acc[j][2], acc[j][3]));
    }
    mxA = fmaxf(mxA, __shfl_xor_sync(0xffffffffu, mxA, 1));
    mxA = fmaxf(mxA, __shfl_xor_sync(0xffffffffu, mxA, 2));
    mxB = fmaxf(mxB, __shfl_xor_sync(0xffffffffu, mxB, 1));
    mxB = fmaxf(mxB, __shfl_xor_sync(0xffffffffu, mxB, 2));
    float sumA = 0.0f, sumB = 0.0f;
#pragma unroll
    for (int j = 0; j < 8; j++) {
        acc[j][0] = __expf(acc[j][0] - mxA); acc[j][1] = __expf(acc[j][1] - mxA);
        acc[j][2] = __expf(acc[j][2] - mxB); acc[j][3] = __expf(acc[j][3] - mxB);
        sumA += acc[j][0] + acc[j][1];
        sumB += acc[j][2] + acc[j][3];
    }
    sumA += __shfl_xor_sync(0xffffffffu, sumA, 1);
    sumA += __shfl_xor_sync(0xffffffffu, sumA, 2);
    sumB += __shfl_xor_sync(0xffffffffu, sumB, 1);
    sumB += __shfl_xor_sync(0xffffffffu, sumB, 2);
    const float invA = 1.0f / sumA, invB = 1.0f / sumB;

    if (EPI == 1) {
#pragma unroll
        for (int j = 0; j < 8; j++) {
            e1->zs[warp_row + g    ][8 * j + 2 * t    ] = acc[j][0] * invA;
            e1->zs[warp_row + g    ][8 * j + 2 * t + 1] = acc[j][1] * invA;
            e1->zs[warp_row + g + 8][8 * j + 2 * t    ] = acc[j][2] * invB;
            e1->zs[warp_row + g + 8][8 * j + 2 * t + 1] = acc[j][3] * invB;
        }
        __syncthreads();
        float* dst = zout + ((size_t)b * NN + rowbase + lrow) * KK + lseg * 32;
        const float* src = &e1->zs[lrow][lseg * 32];
#pragma unroll
        for (int q = 0; q < 8; q++) ((float4*)dst)[q] = ((const float4*)src)[q];
        return;
    }

    // EPI == 0: stage z^T split bf16
#pragma unroll
    for (int j = 0; j < 8; j++) {
        __nv_bfloat16 hi, lo;
        split_bf16(acc[j][0] * invA, hi, lo);
        e0->zh[8 * j + 2 * t    ][warp_row + g    ] = hi; e0->zl[8 * j + 2 * t    ][warp_row + g    ] = lo;
        split_bf16(acc[j][1] * invA, hi, lo);
        e0->zh[8 * j + 2 * t + 1][warp_row + g    ] = hi; e0->zl[8 * j + 2 * t + 1][warp_row + g    ] = lo;
        split_bf16(acc[j][2] * invB, hi, lo);
        e0->zh[8 * j + 2 * t    ][warp_row + g + 8] = hi; e0->zl[8 * j + 2 * t    ][warp_row + g + 8] = lo;
        split_bf16(acc[j][3] * invB, hi, lo);
        e0->zh[8 * j + 2 * t + 1][warp_row + g + 8] = hi; e0->zl[8 * j + 2 * t + 1][warp_row + g + 8] = lo;
    }
    __syncthreads();
    {   // coalesced z^T global write: 64 k-rows x 128 n
        const int k = tid >> 2, q = tid & 3;
        __nv_bfloat16* dh = g_zthi + ((size_t)(b * KK + k)) * NN + rowbase + q * 32;
        __nv_bfloat16* dl = g_ztlo + ((size_t)(b * KK + k)) * NN + rowbase + q * 32;
        const __nv_bfloat16* sh = &e0->zh[k][q * 32];
        const __nv_bfloat16* sl = &e0->zl[k][q * 32];
#pragma unroll
        for (int r = 0; r < 4; r++) {
            ((uint4*)dh)[r] = ((const uint4*)sh)[r];
            ((uint4*)dl)[r] = ((const uint4*)sl)[r];
        }
    }
    if (tid < 64) {  // deterministic column sums over this n-block
        float s = 0.0f;
#pragma unroll 8
        for (int n = 0; n < 128; n++)
            s += __bfloat162float(e0->zh[tid][n]) + __bfloat162float(e0->zl[tid][n]);
        g_Spart[(blockIdx.x * BB + b) * KK + tid] = s;
    }
}

// -------- small reductions --------
__global__ void k_sumS() {
    int b = blockIdx.x, k = threadIdx.x;
    float s = 0.0f;
    for (int r = 0; r < NBLK1; r++) s += g_Spart[(r * BB + b) * KK + k];
    g_S[b * KK + k] = s;
}
__global__ void k_reduceScale() {
    int c = blockIdx.x, b = blockIdx.y, k = threadIdx.x;
    float s = 0.0f;
    size_t base = (((size_t)(b * NSPLIT)) * CC + c) * KK + k;
#pragma unroll 4
    for (int sp = 0; sp < NSPLIT; sp++) s += g_part[base + (size_t)sp * CC * KK];
    g_mtmp[(b * CC + c) * KK + k] = s / (EPSF + g_S[b * KK + k]);
}
__global__ void k_l2norm() {
    int k = blockIdx.x, b = blockIdx.y, c = threadIdx.x;   // 256 threads
    float v = g_mtmp[(b * CC + c) * KK + k];
    float sq = v * v;
#pragma unroll
    for (int m = 16; m; m >>= 1) sq += __shfl_xor_sync(0xffffffffu, sq, m);
    __shared__ float red[8];
    if ((threadIdx.x & 31) == 0) red[threadIdx.x >> 5] = sq;
    __syncthreads();
    float total = 0.0f;
#pragma unroll
    for (int w = 0; w < 8; w++) total += red[w];
    float out = v / (EPSF + sqrtf(total));
    __nv_bfloat16 hi, lo; split_bf16(out, hi, lo);
    size_t o = ((size_t)b * KK + k) * CC + c;
    g_mthi[o] = hi; g_mtlo[o] = lo;
}

// -------- launch --------
extern "C" void kernel_launch(void* const* d_in, const int* in_sizes, int n_in,
                              void* d_out, int out_size) {
    const float* x  = (const float*)d_in[0];
    const float* mu = (const float*)d_in[1];
    if (n_in >= 2 && in_sizes[0] < in_sizes[1]) { const float* tp = x; x = mu; mu = tp; }
    float* z = (float*)d_out;

    static int smem_set = 0;
    if (!smem_set) {
        cudaFuncSetAttribute(k_mma<0>, cudaFuncAttributeMaxDynamicSharedMemorySize, SMEM_MAIN);
        cudaFuncSetAttribute(k_mma<1>, cudaFuncAttributeMaxDynamicSharedMemorySize, SMEM_MAIN);
        cudaFuncSetAttribute(k_mma<2>, cudaFuncAttributeMaxDynamicSharedMemorySize, SMEM_MAIN);
        smem_set = 1;
    }

    k_prep<<<dim3(NN / 32, CC / 32, BB), dim3(32, 8)>>>(x);
    k_initm<<<(BB * KK * CC) / 256, 256>>>(mu);

    for (int s = 0; s < EM_STEPS; s++) {
        k_mma<0><<<dim3(NBLK1, BB), 256, SMEM_MAIN>>>(nullptr);
        k_mma<2><<<dim3(CC / 128, NSPLIT, BB), 256, SMEM_MAIN>>>(nullptr);
        k_sumS<<<BB, KK>>>();
        k_reduceScale<<<dim3(CC, BB), KK>>>();
        k_l2norm<<<dim3(KK, BB), 256>>>();
    }
    // final soft assignment: NO temperature in the reference here
    k_mma<1><<<dim3(NBLK1, BB), 256, SMEM_MAIN>>>(z);
}

// round 14
// speedup vs baseline: 1.2728x; 1.2728x over previous
#include <cuda_runtime.h>
#include <cuda_bf16.h>
#include <cstdint>
#include <math.h>

#define BB   16
#define CC   256
#define NN   16384
#define KK   64
#define TEMPF 20.0f
#define EPSF  1e-6f
#define EM_STEPS 3
#define NSPLIT 32
#define NBLK1 (NN/128)      // 128 GEMM1 n-blocks

// -------- scratch (no allocations allowed -> device globals) --------
__device__ __align__(16) __nv_bfloat16 g_xchi[(size_t)BB*CC*NN];  // x hi   [b][c][n]
__device__ __align__(16) __nv_bfloat16 g_xclo[(size_t)BB*CC*NN];
__device__ __align__(16) __nv_bfloat16 g_zthi[(size_t)BB*KK*NN];  // z^T hi [b][k][n]
__device__ __align__(16) __nv_bfloat16 g_ztlo[(size_t)BB*KK*NN];
__device__ __align__(16) __nv_bfloat16 g_mthi[BB*KK*CC];          // m^T hi [b][k][c]
__device__ __align__(16) __nv_bfloat16 g_mtlo[BB*KK*CC];
__device__ float g_mtmp [BB*CC*KK];
__device__ float g_S    [BB*KK];
__device__ float g_Spart[NBLK1*BB*KK];
__device__ float g_part [(size_t)BB*NSPLIT*CC*KK];

// -------- helpers --------
__device__ __forceinline__ uint32_t smem_u32(const void* p) {
    uint32_t a;
    asm("{ .reg .u64 t; cvta.to.shared.u64 t, %1; cvt.u32.u64 %0, t; }" : "=r"(a) : "l"(p));
    return a;
}
__device__ __forceinline__ void ldm_x4(uint32_t r[4], uint32_t addr) {
    asm volatile("ldmatrix.sync.aligned.m8n8.x4.shared.b16 {%0,%1,%2,%3}, [%4];"
        : "=r"(r[0]), "=r"(r[1]), "=r"(r[2]), "=r"(r[3]) : "r"(addr));
}
__device__ __forceinline__ void ldm_x4t(uint32_t r[4], uint32_t addr) {
    asm volatile("ldmatrix.sync.aligned.m8n8.x4.trans.shared.b16 {%0,%1,%2,%3}, [%4];"
        : "=r"(r[0]), "=r"(r[1]), "=r"(r[2]), "=r"(r[3]) : "r"(addr));
}
__device__ __forceinline__ void mma16816(float c[4], const uint32_t a[4], uint32_t b0, uint32_t b1) {
    asm volatile("mma.sync.aligned.m16n8k16.row.col.f32.bf16.bf16.f32 "
        "{%0,%1,%2,%3}, {%4,%5,%6,%7}, {%8,%9}, {%0,%1,%2,%3};"
        : "+f"(c[0]), "+f"(c[1]), "+f"(c[2]), "+f"(c[3])
        : "r"(a[0]), "r"(a[1]), "r"(a[2]), "r"(a[3]), "r"(b0), "r"(b1));
}
__device__ __forceinline__ void split_bf16(float v, __nv_bfloat16& hi, __nv_bfloat16& lo) {
    hi = __float2bfloat16_rn(v);
    lo = __float2bfloat16_rn(v - __bfloat162float(hi));
}
#define CP16(d, s)  asm volatile("cp.async.cg.shared.global [%0], [%1], 16;" :: "r"(d), "l"(s))
#define CP_COMMIT() asm volatile("cp.async.commit_group;" ::: "memory")
#define CP_WAIT1()  asm volatile("cp.async.wait_group 1;" ::: "memory")
#define CP_WAIT0()  asm volatile("cp.async.wait_group 0;" ::: "memory")

// smem layouts over one dynamic buffer (2-stage pipeline)
struct TilesG1 {                                 // GEMM1 stage: 27648 B
    __nv_bfloat16 ah[32][136], al[32][136];      // A^T: 32 ctr(c) rows x 128 n (+8 pad)
    __nv_bfloat16 bh[64][40],  bl[64][40];       // B: 64 k-rows x 32 ctr (+8 pad)
};
struct TilesG2 {                                 // GEMM2 stage: 30720 B
    __nv_bfloat16 ah[128][40], al[128][40];      // A: 128 c-rows x 32 ctr(n) (+8 pad)
    __nv_bfloat16 bh[64][40],  bl[64][40];       // B: 64 k-rows x 32 ctr (+8 pad)
};
struct E0 { __nv_bfloat16 zh[64][144], zl[64][144]; };  // 36864 B
struct E1 { float zs[128][72]; };                        // 36864 B
#define SMEM_MAIN 61440                           // 2 * sizeof(TilesG2)

// -------- prepass: x fp32 -> split bf16, same orientation, pure streaming --------
__global__ void k_prep(const float4* __restrict__ x4) {
    size_t i = (size_t)blockIdx.x * 256 + threadIdx.x;    // over BB*CC*NN/4
    float4 v = x4[i];
    __nv_bfloat16 h0, l0, h1, l1, h2, l2, h3, l3;
    split_bf16(v.x, h0, l0); split_bf16(v.y, h1, l1);
    split_bf16(v.z, h2, l2); split_bf16(v.w, h3, l3);
    union { __nv_bfloat16 h[4]; uint2 u; } ph, pl;
    ph.h[0] = h0; ph.h[1] = h1; ph.h[2] = h2; ph.h[3] = h3;
    pl.h[0] = l0; pl.h[1] = l1; pl.h[2] = l2; pl.h[3] = l3;
    ((uint2*)g_xchi)[i] = ph.u;
    ((uint2*)g_xclo)[i] = pl.u;
}

// -------- init m^T from mu (broadcast over batches) --------
__global__ void k_initm(const float* __restrict__ mu) {
    int idx = blockIdx.x * 256 + threadIdx.x;       // over B*K*C, c fastest
    int c = idx & (CC - 1);
    int k = (idx >> 8) & (KK - 1);
    __nv_bfloat16 hi, lo; split_bf16(mu[c * KK + k], hi, lo);
    g_mthi[idx] = hi; g_mtlo[idx] = lo;
}

// ---- unified MMA kernel (2-stage cp.async pipeline; A via ldmatrix[.trans]) ----
// EPI 0: GEMM1 EM step  : softmax(TEMP*logits) -> z^T split bf16 + column-sum partials
// EPI 1: GEMM1 final    : softmax(logits) -> fp32 z to d_out
// EPI 2: GEMM2 partials : raw fp32 partial sums to g_part
template<int EPI>
__global__ void __launch_bounds__(256)
k_mma(float* __restrict__ zout) {
    extern __shared__ __align__(16) char dynsmem[];
    TilesG1* t1 = (TilesG1*)dynsmem;
    TilesG2* t2 = (TilesG2*)dynsmem;
    E0* e0 = (E0*)dynsmem;
    E1* e1 = (E1*)dynsmem;

    const int tid  = threadIdx.x;
    const int lane = tid & 31, warp = tid >> 5;
    const int g = lane >> 2, t = lane & 3;
    const int warp_row = warp * 16;

    const __nv_bfloat16 *Ah, *Al, *Bh, *Bl;
    int ctr0, iters, b, rowbase;
    if (EPI < 2) {
        b = blockIdx.y; rowbase = blockIdx.x * 128;           // n-block
        Ah = g_xchi + (size_t)b * CC * NN;                    // [c][n], c = contraction
        Al = g_xclo + (size_t)b * CC * NN;
        Bh = g_mthi + (size_t)b * KK * CC;                    // [k][c]
        Bl = g_mtlo + (size_t)b * KK * CC;
        ctr0 = 0; iters = CC / 32;
    } else {
        b = blockIdx.z; rowbase = blockIdx.x * 128;           // c-block
        Ah = g_xchi + ((size_t)b * CC + rowbase) * NN;        // [c][n], n = contraction
        Al = g_xclo + ((size_t)b * CC + rowbase) * NN;
        Bh = g_zthi + (size_t)b * KK * NN;                    // [k][n]
        Bl = g_ztlo + (size_t)b * KK * NN;
        ctr0 = blockIdx.y * (NN / NSPLIT); iters = (NN / NSPLIT) / 32;
    }

    float acc[8][4];
#pragma unroll
    for (int j = 0; j < 8; j++)
#pragma unroll
        for (int r = 0; r < 4; r++) acc[j][r] = 0.0f;

    // fill thread mappings
    const int lrow = tid >> 1, lseg = tid & 1;     // G2 A: 128 rows x 2 segs
    const int arow = tid >> 3, aseg = tid & 7;     // G1 A: 32 rows x 8 segs (16 elems each)
    const int brow = tid >> 2, bseg = tid & 3;     // B: 64 rows x 4 segs

    auto fill = [&](int it, int buf) {
        const int c0 = ctr0 + it * 32;
        if (EPI < 2) {
            TilesG1& T = t1[buf];
            {   // A^T tile: 32 c-rows x 128 n, source row stride NN
                uint32_t d = smem_u32(&T.ah[arow][aseg * 16]);
                const __nv_bfloat16* s = Ah + (size_t)(c0 + arow) * NN + rowbase + aseg * 16;
                CP16(d, s); CP16(d + 16, s + 8);
                d = smem_u32(&T.al[arow][aseg * 16]);
                s = Al + (size_t)(c0 + arow) * NN + rowbase + aseg * 16;
                CP16(d, s); CP16(d + 16, s + 8);
            }
            {   // B tile: 64 k-rows x 32 c, source row stride CC
                uint32_t d = smem_u32(&T.bh[brow][bseg * 8]);
                const __nv_bfloat16* s = Bh + (size_t)brow * CC + c0 + bseg * 8;
                CP16(d, s);
                d = smem_u32(&T.bl[brow][bseg * 8]);
                s = Bl + (size_t)brow * CC + c0 + bseg * 8;
                CP16(d, s);
            }
        } else {
            TilesG2& T = t2[buf];
            {   // A tile: 128 c-rows x 32 n, source row stride NN
                uint32_t d = smem_u32(&T.ah[lrow][lseg * 16]);
                const __nv_bfloat16* s = Ah + (size_t)lrow * NN + c0 + lseg * 16;
                CP16(d, s); CP16(d + 16, s + 8);
                d = smem_u32(&T.al[lrow][lseg * 16]);
                s = Al + (size_t)lrow * NN + c0 + lseg * 16;
                CP16(d, s); CP16(d + 16, s + 8);
            }
            {   // B tile: 64 k-rows x 32 n, source row stride NN
                uint32_t d = smem_u32(&T.bh[brow][bseg * 8]);
                const __nv_bfloat16* s = Bh + (size_t)brow * NN + c0 + bseg * 8;
                CP16(d, s);
                d = smem_u32(&T.bl[brow][bseg * 8]);
                s = Bl + (size_t)brow * NN + c0 + bseg * 8;
                CP16(d, s);
            }
        }
        CP_COMMIT();
    };

    fill(0, 0);
    for (int it = 0; it < iters; it++) {
        if (it + 1 < iters) { fill(it + 1, (it + 1) & 1); CP_WAIT1(); }
        else                { CP_WAIT0(); }
        __syncthreads();
        const int buf = it & 1;

#pragma unroll
        for (int ks = 0; ks < 2; ks++) {
            const int lr = lane & 7, lq = lane >> 3;
            uint32_t ah4[4], al4[4];
            if (EPI < 2) {
                // A^T stored [c][n]: transposed 8x8 loads; q0=(m0-7,k0-7) q1=(m8-15,k0-7)
                // q2=(m0-7,k8-15) q3=(m8-15,k8-15) via row=k-half(q>>1), col=m-half(q&1)
                ldm_x4t(ah4, smem_u32(&t1[buf].ah[ks * 16 + (lq >> 1) * 8 + lr][warp_row + (lq & 1) * 8]));
                ldm_x4t(al4, smem_u32(&t1[buf].al[ks * 16 + (lq >> 1) * 8 + lr][warp_row + (lq & 1) * 8]));
            } else {
                ldm_x4(ah4, smem_u32(&t2[buf].ah[warp_row + lr + (lq & 1) * 8][ks * 16 + (lq >> 1) * 8]));
                ldm_x4(al4, smem_u32(&t2[buf].al[warp_row + lr + (lq & 1) * 8][ks * 16 + (lq >> 1) * 8]));
            }
            // B fragments (same smem offsets in both tile structs)
            __nv_bfloat16 (*bhp)[40] = (EPI < 2) ? t1[buf].bh : t2[buf].bh;
            __nv_bfloat16 (*blp)[40] = (EPI < 2) ? t1[buf].bl : t2[buf].bl;
#pragma unroll
            for (int jp = 0; jp < 4; jp++) {
                uint32_t bh4[4], bl4[4];
                ldm_x4(bh4, smem_u32(&bhp[jp * 16 + (lq >> 1) * 8 + lr][ks * 16 + (lq & 1) * 8]));
                ldm_x4(bl4, smem_u32(&blp[jp * 16 + (lq >> 1) * 8 + lr][ks * 16 + (lq & 1) * 8]));
                mma16816(acc[jp * 2    ], ah4, bh4[0], bh4[1]);   // hi*hi
                mma16816(acc[jp * 2    ], ah4, bl4[0], bl4[1]);   // hi*lo
                mma16816(acc[jp * 2    ], al4, bh4[0], bh4[1]);   // lo*hi
                mma16816(acc[jp * 2 + 1], ah4, bh4[2], bh4[3]);
                mma16816(acc[jp * 2 + 1], ah4, bl4[2], bl4[3]);
                mma16816(acc[jp * 2 + 1], al4, bh4[2], bh4[3]);
            }
        }
        __syncthreads();
    }

    if (EPI == 2) {
#pragma unroll
        for (int j = 0; j < 8; j++) {
            e1->zs[warp_row + g    ][8 * j + 2 * t    ] = acc[j][0];
            e1->zs[warp_row + g    ][8 * j + 2 * t + 1] = acc[j][1];
            e1->zs[warp_row + g + 8][8 * j + 2 * t    ] = acc[j][2];
            e1->zs[warp_row + g + 8][8 * j + 2 * t + 1] = acc[j][3];
        }
        __syncthreads();
        const int split = blockIdx.y;
        float* dst = g_part + (((size_t)(b * NSPLIT + split)) * CC + rowbase + lrow) * KK + lseg * 32;
        const float* src = &e1->zs[lrow][lseg * 32];
#pragma unroll
        for (int q = 0; q < 8; q++) ((float4*)dst)[q] = ((const float4*)src)[q];
        return;
    }

    // GEMM1 epilogues: softmax over k (rows warp_row+g and warp_row+g+8)
    const float sc = (EPI == 0) ? TEMPF : 1.0f;
    float mxA = -1e30f, mxB = -1e30f;
#pragma unroll
    for (int j = 0; j < 8; j++) {
        acc[j][0] *= sc; acc[j][1] *= sc; acc[j][2] *= sc; acc[j][3] *= sc;
        mxA = fmaxf(mxA, fmaxf(acc[j][0], acc[j][1]));
        mxB = fmaxf(mxB, fmaxf(acc[j][2], acc[j][3]));
    }
    mxA = fmaxf(mxA, __shfl_xor_sync(0xffffffffu, mxA, 1));
    mxA = fmaxf(mxA, __shfl_xor_sync(0xffffffffu, mxA, 2));
    mxB = fmaxf(mxB, __shfl_xor_sync(0xffffffffu, mxB, 1));
    mxB = fmaxf(mxB, __shfl_xor_sync(0xffffffffu, mxB, 2));
    float sumA = 0.0f, sumB = 0.0f;
#pragma unroll
    for (int j = 0; j < 8; j++) {
        acc[j][0] = __expf(acc[j][0] - mxA); acc[j][1] = __expf(acc[j][1] - mxA);
        acc[j][2] = __expf(acc[j][2] - mxB); acc[j][3] = __expf(acc[j][3] - mxB);
        sumA += acc[j][0] + acc[j][1];
        sumB += acc[j][2] + acc[j][3];
    }
    sumA += __shfl_xor_sync(0xffffffffu, sumA, 1);
    sumA += __shfl_xor_sync(0xffffffffu, sumA, 2);
    sumB += __shfl_xor_sync(0xffffffffu, sumB, 1);
    sumB += __shfl_xor_sync(0xffffffffu, sumB, 2);
    const float invA = 1.0f / sumA, invB = 1.0f / sumB;

    if (EPI == 1) {
#pragma unroll
        for (int j = 0; j < 8; j++) {
            e1->zs[warp_row + g    ][8 * j + 2 * t    ] = acc[j][0] * invA;
            e1->zs[warp_row + g    ][8 * j + 2 * t + 1] = acc[j][1] * invA;
            e1->zs[warp_row + g + 8][8 * j + 2 * t    ] = acc[j][2] * invB;
            e1->zs[warp_row + g + 8][8 * j + 2 * t + 1] = acc[j][3] * invB;
        }
        __syncthreads();
        float* dst = zout + ((size_t)b * NN + rowbase + lrow) * KK + lseg * 32;
        const float* src = &e1->zs[lrow][lseg * 32];
#pragma unroll
        for (int q = 0; q < 8; q++) ((float4*)dst)[q] = ((const float4*)src)[q];
        return;
    }

    // EPI == 0: stage z^T split bf16
#pragma unroll
    for (int j = 0; j < 8; j++) {
        __nv_bfloat16 hi, lo;
        split_bf16(acc[j][0] * invA, hi, lo);
        e0->zh[8 * j + 2 * t    ][warp_row + g    ] = hi; e0->zl[8 * j + 2 * t    ][warp_row + g    ] = lo;
        split_bf16(acc[j][1] * invA, hi, lo);
        e0->zh[8 * j + 2 * t + 1][warp_row + g    ] = hi; e0->zl[8 * j + 2 * t + 1][warp_row + g    ] = lo;
        split_bf16(acc[j][2] * invB, hi, lo);
        e0->zh[8 * j + 2 * t    ][warp_row + g + 8] = hi; e0->zl[8 * j + 2 * t    ][warp_row + g + 8] = lo;
        split_bf16(acc[j][3] * invB, hi, lo);
        e0->zh[8 * j + 2 * t + 1][warp_row + g + 8] = hi; e0->zl[8 * j + 2 * t + 1][warp_row + g + 8] = lo;
    }
    __syncthreads();
    {   // coalesced z^T global write: 64 k-rows x 128 n
        const int k = tid >> 2, q = tid & 3;
        __nv_bfloat16* dh = g_zthi + ((size_t)(b * KK + k)) * NN + rowbase + q * 32;
        __nv_bfloat16* dl = g_ztlo + ((size_t)(b * KK + k)) * NN + rowbase + q * 32;
        const __nv_bfloat16* sh = &e0->zh[k][q * 32];
        const __nv_bfloat16* sl = &e0->zl[k][q * 32];
#pragma unroll
        for (int r = 0; r < 4; r++) {
            ((uint4*)dh)[r] = ((const uint4*)sh)[r];
            ((uint4*)dl)[r] = ((const uint4*)sl)[r];
        }
    }
    if (tid < 64) {  // deterministic column sums over this n-block
        float s = 0.0f;
#pragma unroll 8
        for (int n = 0; n < 128; n++)
            s += __bfloat162float(e0->zh[tid][n]) + __bfloat162float(e0->zl[tid][n]);
        g_Spart[(blockIdx.x * BB + b) * KK + tid] = s;
    }
}

// -------- small reductions --------
__global__ void k_sumS() {
    int b = blockIdx.x, k = threadIdx.x;
    float s = 0.0f;
    for (int r = 0; r < NBLK1; r++) s += g_Spart[(r * BB + b) * KK + k];
    g_S[b * KK + k] = s;
}
__global__ void k_reduceScale() {
    int c = blockIdx.x, b = blockIdx.y, k = threadIdx.x;
    float s = 0.0f;
    size_t base = (((size_t)(b * NSPLIT)) * CC + c) * KK + k;
#pragma unroll 4
    for (int sp = 0; sp < NSPLIT; sp++) s += g_part[base + (size_t)sp * CC * KK];
    g_mtmp[(b * CC + c) * KK + k] = s / (EPSF + g_S[b * KK + k]);
}
__global__ void k_l2norm() {
    int k = blockIdx.x, b = blockIdx.y, c = threadIdx.x;   // 256 threads
    float v = g_mtmp[(b * CC + c) * KK + k];
    float sq = v * v;
#pragma unroll
    for (int m = 16; m; m >>= 1) sq += __shfl_xor_sync(0xffffffffu, sq, m);
    __shared__ float red[8];
    if ((threadIdx.x & 31) == 0) red[threadIdx.x >> 5] = sq;
    __syncthreads();
    float total = 0.0f;
#pragma unroll
    for (int w = 0; w < 8; w++) total += red[w];
    float out = v / (EPSF + sqrtf(total));
    __nv_bfloat16 hi, lo; split_bf16(out, hi, lo);
    size_t o = ((size_t)b * KK + k) * CC + c;
    g_mthi[o] = hi; g_mtlo[o] = lo;
}

// -------- launch --------
extern "C" void kernel_launch(void* const* d_in, const int* in_sizes, int n_in,
                              void* d_out, int out_size) {
    const float* x  = (const float*)d_in[0];
    const float* mu = (const float*)d_in[1];
    if (n_in >= 2 && in_sizes[0] < in_sizes[1]) { const float* tp = x; x = mu; mu = tp; }
    float* z = (float*)d_out;

    static int smem_set = 0;
    if (!smem_set) {
        cudaFuncSetAttribute(k_mma<0>, cudaFuncAttributeMaxDynamicSharedMemorySize, SMEM_MAIN);
        cudaFuncSetAttribute(k_mma<1>, cudaFuncAttributeMaxDynamicSharedMemorySize, SMEM_MAIN);
        cudaFuncSetAttribute(k_mma<2>, cudaFuncAttributeMaxDynamicSharedMemorySize, SMEM_MAIN);
        smem_set = 1;
    }

    k_prep<<<(BB * CC * NN / 4) / 256, 256>>>((const float4*)x);
    k_initm<<<(BB * KK * CC) / 256, 256>>>(mu);

    for (int s = 0; s < EM_STEPS; s++) {
        k_mma<0><<<dim3(NBLK1, BB), 256, SMEM_MAIN>>>(nullptr);
        k_mma<2><<<dim3(CC / 128, NSPLIT, BB), 256, SMEM_MAIN>>>(nullptr);
        k_sumS<<<BB, KK>>>();
        k_reduceScale<<<dim3(CC, BB), KK>>>();
        k_l2norm<<<dim3(KK, BB), 256>>>();
    }
    // final soft assignment: NO temperature in the reference here
    k_mma<1><<<dim3(NBLK1, BB), 256, SMEM_MAIN>>>(z);
}